// round 16
// baseline (speedup 1.0000x reference)
#include <cuda_runtime.h>
#include <cuda_fp16.h>
#include <math.h>
#include <cstdint>

#define BB 8192
#define DD 256
#define NCLS 128
#define HCAP (1<<20)

// ---------------- scratch ----------------
__device__ int    g_lab[BB];
__device__ __half g_h[BB*DD];
__device__ float  g_S[NCLS*DD];
__device__ int    g_cnt[NCLS];
__device__ float  g_rowsum[BB];
__device__ float  g_hsum[BB];
__device__ int    g_hcnt[BB];
__device__ int    g_hn;
__device__ int    g_hrow[HCAP];
__device__ float  g_hval[HCAP];

__device__ __forceinline__ uint32_t smem_u32(const void* p) {
    uint32_t a;
    asm("{ .reg .u64 t; cvta.to.shared.u64 t, %1; cvt.u32.u64 %0, t; }" : "=r"(a) : "l"(p));
    return a;
}

#define LDM_X4(r0,r1,r2,r3,addr) \
    asm volatile("ldmatrix.sync.aligned.m8n8.x4.shared.b16 {%0,%1,%2,%3}, [%4];" \
        : "=r"(r0), "=r"(r1), "=r"(r2), "=r"(r3) : "r"(addr))

#define MMA_F16(c, a0,a1,a2,a3, b0,b1) \
    asm volatile("mma.sync.aligned.m16n8k16.row.col.f32.f16.f16.f32 " \
        "{%0,%1,%2,%3}, {%4,%5,%6,%7}, {%8,%9}, {%0,%1,%2,%3};" \
        : "+f"((c)[0]), "+f"((c)[1]), "+f"((c)[2]), "+f"((c)[3]) \
        : "r"(a0), "r"(a1), "r"(a2), "r"(a3), "r"(b0), "r"(b1))

__device__ __forceinline__ void cp16(uint32_t dst, const void* src) {
    asm volatile("cp.async.cg.shared.global [%0], [%1], 16;" :: "r"(dst), "l"(src));
}
#define CP_COMMIT() asm volatile("cp.async.commit_group;" ::: "memory")
#define CP_WAIT(n)  asm volatile("cp.async.wait_group %0;" :: "n"(n) : "memory")

// fast e^{20x}: 2^{x*20*log2e}, degree-6 poly, relerr ~1e-7
__device__ __forceinline__ float exp20(float x) {
    float y = x * 28.853900817779268f;
    float z = y + 12582912.0f;
    int   zi = __float_as_int(z);
    float f = y - (z - 12582912.0f);
    float p = 1.5403530e-4f;
    p = fmaf(p, f, 1.3333558e-3f);
    p = fmaf(p, f, 9.6181291e-3f);
    p = fmaf(p, f, 5.5504109e-2f);
    p = fmaf(p, f, 2.4022651e-1f);
    p = fmaf(p, f, 6.9314718e-1f);
    p = fmaf(p, f, 1.0f);
    return __int_as_float(__float_as_int(p) + (zi << 23));
}

// ---------------- prep ----------------
__global__ void prep_kernel(const int* __restrict__ labraw) {
    __shared__ int is64_s;
    if (threadIdx.x == 0) {
        int all0 = 1;
        #pragma unroll
        for (int i = 0; i < 64; i++) all0 &= (labraw[2*i + 1] == 0);
        is64_s = all0;
    }
    __syncthreads();
    int is64 = is64_s;
    int tid = blockIdx.x*blockDim.x + threadIdx.x;
    int nt = gridDim.x*blockDim.x;
    for (int i = tid; i < BB; i += nt) g_lab[i] = is64 ? labraw[2*i] : labraw[i];
    for (int i = tid; i < NCLS*DD; i += nt) g_S[i] = 0.f;
    for (int i = tid; i < NCLS; i += nt) g_cnt[i] = 0;
    for (int i = tid; i < BB; i += nt) { g_hsum[i] = 0.f; g_hcnt[i] = 0; g_rowsum[i] = 0.f; }
    if (tid == 0) g_hn = 0;
}

// ---------------- normalize + fp16 cast + class sums ----------------
__global__ void norm_kernel(const float* __restrict__ feat) {
    int warp = threadIdx.x >> 5, lane = threadIdx.x & 31;
    int row = blockIdx.x*8 + warp;
    const float* fr = feat + (size_t)row*DD;
    float v[8]; float ss = 0.f;
    #pragma unroll
    for (int j = 0; j < 8; j++) { v[j] = fr[lane + j*32]; ss += v[j]*v[j]; }
    #pragma unroll
    for (int off = 16; off > 0; off >>= 1) ss += __shfl_xor_sync(0xffffffffu, ss, off);
    float inv = 1.f / fmaxf(sqrtf(ss), 1e-12f);
    int c = g_lab[row];
    #pragma unroll
    for (int j = 0; j < 8; j++) {
        float fnv = v[j]*inv;
        g_h[(size_t)row*DD + lane + j*32] = __float2half(fnv);
        atomicAdd(&g_S[c*DD + lane + j*32], fnv);
    }
    if (lane == 0) atomicAdd(&g_cnt[c], 1);
}

// ---------------- triangular fp16 mma.sync main kernel ----------------
// One 128x128 tile per CTA, rb <= cb. K chunked by 64, cp.async double-buffered,
// single __syncthreads per chunk.
#define KC 64
#define STR 72                       // 64 k elems + 8 pad (halves)
#define MAT (128*STR*2)              // 18432 B per matrix per stage
#define STAGE (2*MAT)                // A, B
#define SM_TOTAL (2*STAGE)           // 73728 B -> 2 CTAs/SM

__device__ __forceinline__ void load_chunk(uint32_t sb, int stage,
                                           int rowbase, int colbase, int kc) {
    int tid = threadIdx.x;
    uint32_t sbase = sb + stage*STAGE;
    #pragma unroll
    for (int m = 0; m < 2; m++) {
        int base = (m == 0) ? rowbase : colbase;
        #pragma unroll
        for (int i = 0; i < 4; i++) {
            int idx = tid + i*256;
            int row = idx >> 3;
            int kq = (idx & 7) * 8;
            uint32_t dst = sbase + m*MAT + (uint32_t)(row*STR + kq)*2;
            cp16(dst, &g_h[(size_t)(base+row)*DD + kc*KC + kq]);
        }
    }
}

__global__ void __launch_bounds__(256, 2)
main_tc() {
    extern __shared__ char smem[];
    uint32_t sb = smem_u32(smem);
    int tid = threadIdx.x;
    int wid = tid >> 5, l = tid & 31;
    int warpM = wid >> 2;
    int warpN = wid & 3;

    // decode triangular tile index -> (rb, cb), rb <= cb
    int rb = 0, rem = blockIdx.x;
    while (rem >= 64 - rb) { rem -= 64 - rb; rb++; }
    int cb = rb + rem;
    int rowbase = rb * 128;
    int colbase = cb * 128;
    bool isdiag = (rb == cb);

    uint32_t aOff = (uint32_t)((warpM*64 + (l & 15))*STR*2 + (l >> 4)*16);
    int bRow = (l & 7) + ((l >> 4) << 3);
    uint32_t bOff = (uint32_t)((warpN*32 + bRow)*STR*2 + ((l >> 3) & 1)*16);

    float acc[64];
    #pragma unroll
    for (int i = 0; i < 64; i++) acc[i] = 0.f;

    load_chunk(sb, 0, rowbase, colbase, 0);
    CP_COMMIT();

    #pragma unroll 1
    for (int c = 0; c < 4; ++c) {
        // chunk c resident after this wait (its commit was the last pending group)
        CP_WAIT(0);
        __syncthreads();
        // prefetch c+1 into stage (c+1)&1: that buffer held chunk c-1, whose
        // compute finished on ALL warps before the sync above.
        if (c < 3) { load_chunk(sb, (c + 1) & 1, rowbase, colbase, c + 1); CP_COMMIT(); }

        uint32_t st = sb + (c & 1)*STAGE;
        uint32_t sA = st, sB = st + MAT;

        #pragma unroll
        for (int ks = 0; ks < 4; ++ks) {
            uint32_t ka = (uint32_t)(ks*32);
            uint32_t a0[16], b0[8];
            #pragma unroll
            for (int mt = 0; mt < 4; ++mt) {
                uint32_t aa = sA + aOff + (uint32_t)(mt*16*STR*2) + ka;
                LDM_X4(a0[mt*4+0], a0[mt*4+1], a0[mt*4+2], a0[mt*4+3], aa);
            }
            {
                uint32_t bb0 = sB + bOff + ka;
                uint32_t bb1 = bb0 + (uint32_t)(16*STR*2);
                LDM_X4(b0[0], b0[1], b0[2], b0[3], bb0);
                LDM_X4(b0[4], b0[5], b0[6], b0[7], bb1);
            }
            #pragma unroll
            for (int mt = 0; mt < 4; ++mt)
                #pragma unroll
                for (int nt = 0; nt < 4; ++nt)
                    MMA_F16(&acc[(mt*4+nt)*4], a0[mt*4+0], a0[mt*4+1], a0[mt*4+2], a0[mt*4+3],
                            b0[nt*2+0], b0[nt*2+1]);
        }
    }

    // ---- epilogue (R12 form: inline rare-path, acc consumed in-loop) ----
    float rs[8];
    float cq0[4], cq1[4];
    #pragma unroll
    for (int i = 0; i < 8; i++) rs[i] = 0.f;
    #pragma unroll
    for (int i = 0; i < 4; i++) { cq0[i] = 0.f; cq1[i] = 0.f; }

    int grq = rowbase + warpM*64 + (l >> 2);
    #pragma unroll
    for (int mt = 0; mt < 4; ++mt) {
        int gr0 = grq + mt*16;
        int gr1 = gr0 + 8;
        #pragma unroll
        for (int nt = 0; nt < 4; ++nt) {
            const float* cc = &acc[(mt*4+nt)*4];
            int gc0 = colbase + warpN*32 + nt*8 + (l & 3)*2;
            int gc1 = gc0 + 1;
            float e0 = exp20(cc[0]);
            float e1 = exp20(cc[1]);
            float e2 = exp20(cc[2]);
            float e3 = exp20(cc[3]);
            if (isdiag) {
                e0 = (gc0 == gr0) ? 0.f : e0;
                e1 = (gc1 == gr0) ? 0.f : e1;
                e2 = (gc0 == gr1) ? 0.f : e2;
                e3 = (gc1 == gr1) ? 0.f : e3;
            }
            rs[mt*2+0] += e0 + e1;
            rs[mt*2+1] += e2 + e3;
            cq0[nt] += e0 + e2;
            cq1[nt] += e1 + e3;
            // rare path: cosine > 0.7, same label, not self
            if (cc[0] > 0.7f && gc0 != gr0 && g_lab[gc0] == g_lab[gr0]) {
                int idx = atomicAdd(&g_hn, 1);
                if (idx < HCAP) { g_hrow[idx] = gr0; g_hval[idx] = cc[0]*20.f; }
                if (!isdiag) {
                    int idx2 = atomicAdd(&g_hn, 1);
                    if (idx2 < HCAP) { g_hrow[idx2] = gc0; g_hval[idx2] = cc[0]*20.f; }
                }
            }
            if (cc[1] > 0.7f && gc1 != gr0 && g_lab[gc1] == g_lab[gr0]) {
                int idx = atomicAdd(&g_hn, 1);
                if (idx < HCAP) { g_hrow[idx] = gr0; g_hval[idx] = cc[1]*20.f; }
                if (!isdiag) {
                    int idx2 = atomicAdd(&g_hn, 1);
                    if (idx2 < HCAP) { g_hrow[idx2] = gc1; g_hval[idx2] = cc[1]*20.f; }
                }
            }
            if (cc[2] > 0.7f && gc0 != gr1 && g_lab[gc0] == g_lab[gr1]) {
                int idx = atomicAdd(&g_hn, 1);
                if (idx < HCAP) { g_hrow[idx] = gr1; g_hval[idx] = cc[2]*20.f; }
                if (!isdiag) {
                    int idx2 = atomicAdd(&g_hn, 1);
                    if (idx2 < HCAP) { g_hrow[idx2] = gc0; g_hval[idx2] = cc[2]*20.f; }
                }
            }
            if (cc[3] > 0.7f && gc1 != gr1 && g_lab[gc1] == g_lab[gr1]) {
                int idx = atomicAdd(&g_hn, 1);
                if (idx < HCAP) { g_hrow[idx] = gr1; g_hval[idx] = cc[3]*20.f; }
                if (!isdiag) {
                    int idx2 = atomicAdd(&g_hn, 1);
                    if (idx2 < HCAP) { g_hrow[idx2] = gc1; g_hval[idx2] = cc[3]*20.f; }
                }
            }
        }
    }

    // row sums: reduce over the 4 lanes in a quad (same rows), then atomic
    #pragma unroll
    for (int i = 0; i < 8; i++) {
        rs[i] += __shfl_xor_sync(0xffffffffu, rs[i], 1);
        rs[i] += __shfl_xor_sync(0xffffffffu, rs[i], 2);
    }
    if ((l & 3) == 0) {
        #pragma unroll
        for (int i = 0; i < 8; i++) {
            int row = rowbase + warpM*64 + (i >> 1)*16 + (i & 1)*8 + (l >> 2);
            atomicAdd(&g_rowsum[row], rs[i]);
        }
    }
    // column sums (symmetric contribution): reduce over the 8 lanes sharing columns
    if (!isdiag) {
        #pragma unroll
        for (int nt = 0; nt < 4; ++nt) {
            cq0[nt] += __shfl_xor_sync(0xffffffffu, cq0[nt], 4);
            cq0[nt] += __shfl_xor_sync(0xffffffffu, cq0[nt], 8);
            cq0[nt] += __shfl_xor_sync(0xffffffffu, cq0[nt], 16);
            cq1[nt] += __shfl_xor_sync(0xffffffffu, cq1[nt], 4);
            cq1[nt] += __shfl_xor_sync(0xffffffffu, cq1[nt], 8);
            cq1[nt] += __shfl_xor_sync(0xffffffffu, cq1[nt], 16);
        }
        if (l < 4) {
            #pragma unroll
            for (int nt = 0; nt < 4; ++nt) {
                int gc0 = colbase + warpN*32 + nt*8 + l*2;
                atomicAdd(&g_rowsum[gc0], cq0[nt]);
                atomicAdd(&g_rowsum[gc0 + 1], cq1[nt]);
            }
        }
    }
}

// ---------------- finalize: single kernel, 1 CTA ----------------
__global__ void finalize_kernel(float* __restrict__ out) {
    int tid = threadIdx.x;
    // SCL numerator: sum_i (cnt[lab_i]-1) * log(rowsum_i)
    double accscl = 0.0;
    #pragma unroll
    for (int j = 0; j < 8; j++) {
        int i = tid + j*1024;
        float logd = logf(g_rowsum[i] + 1e-30f);
        float np = (float)(g_cnt[g_lab[i]] - 1);
        accscl += (double)np * (double)logd;
    }
    // class-sum norms and counts
    double lssq = 0.0;
    for (int i = tid; i < NCLS*DD; i += 1024) {
        double s = (double)g_S[i];
        lssq += s*s;
    }
    double lcc = 0.0, lc2 = 0.0;
    for (int c = tid; c < NCLS; c += 1024) {
        double cc = (double)g_cnt[c];
        lcc += cc; lc2 += cc*cc;
    }
    // rare relaxation path
    double accrel = 0.0;
    int hn = g_hn; if (hn > HCAP) hn = HCAP;
    if (hn > 0) {
        for (int e = tid; e < hn; e += 1024) {
            int r = g_hrow[e];
            atomicAdd(&g_hsum[r], __expf(g_hval[e] - 20.f));
            atomicAdd(&g_hcnt[r], 1);
        }
        __syncthreads();
        for (int i = tid; i < BB; i += 1024) {
            if (g_hcnt[i] > 0) accrel += (double)log1pf(g_hsum[i]);
        }
    }
    __shared__ double s0[1024], s1[1024], s2[1024], s3[1024], s4[1024];
    s0[tid] = accscl; s1[tid] = lssq; s2[tid] = accrel; s3[tid] = lcc; s4[tid] = lc2;
    __syncthreads();
    for (int st = 512; st > 0; st >>= 1) {
        if (tid < st) {
            s0[tid] += s0[tid+st]; s1[tid] += s1[tid+st]; s2[tid] += s2[tid+st];
            s3[tid] += s3[tid+st]; s4[tid] += s4[tid+st];
        }
        __syncthreads();
    }
    if (tid == 0) {
        double ssq = s1[0], totc = s3[0], c2 = s4[0];
        double npos = c2 - totc;                    // sum cnt*(cnt-1)
        double possum = 20.0 * (ssq - totc);        // ordered positive-pair sim sum
        double scl = (npos > 0.0) ? (s0[0] - possum) / fmax(npos, 1.0) : 0.0;
        int hn2 = g_hn; if (hn2 > HCAP) hn2 = HCAP;
        double rel = (hn2 > 0) ? s2[0] / (double)(hn2 > 1 ? hn2 : 1) : 0.0;
        double tot = scl + rel;
        tot = fmin(fmax(tot, 0.0), 10.0);
        out[0] = (float)tot;
    }
}

extern "C" void kernel_launch(void* const* d_in, const int* in_sizes, int n_in,
                              void* d_out, int out_size) {
    const float* feat = (const float*)d_in[0];
    const int* labraw = (const int*)d_in[1];
    float* out = (float*)d_out;

    static bool attr_set = false;
    if (!attr_set) {
        cudaFuncSetAttribute(main_tc, cudaFuncAttributeMaxDynamicSharedMemorySize, SM_TOTAL);
        attr_set = true;
    }

    prep_kernel<<<64, 256>>>(labraw);
    norm_kernel<<<BB/8, 256>>>(feat);
    main_tc<<<2080, 256, SM_TOTAL>>>();
    finalize_kernel<<<1, 1024>>>(out);
}

// round 17
// speedup vs baseline: 1.2279x; 1.2279x over previous
#include <cuda_runtime.h>
#include <cuda_fp16.h>
#include <math.h>
#include <cstdint>

#define BB 8192
#define DD 256
#define NCLS 128
#define HCAP (1<<20)

// ---------------- scratch ----------------
__device__ int    g_lab[BB];
__device__ __half g_h[BB*DD];
__device__ float  g_S[NCLS*DD];
__device__ int    g_cnt[NCLS];
__device__ float  g_rowsum[BB];
__device__ double g_acc[4];          // accscl, lssq, lcc, lc2
__device__ float  g_hsum[BB];
__device__ int    g_hcnt[BB];
__device__ int    g_hn;
__device__ int    g_hrow[HCAP];
__device__ float  g_hval[HCAP];

__device__ __forceinline__ uint32_t smem_u32(const void* p) {
    uint32_t a;
    asm("{ .reg .u64 t; cvta.to.shared.u64 t, %1; cvt.u32.u64 %0, t; }" : "=r"(a) : "l"(p));
    return a;
}

#define LDM_X4(r0,r1,r2,r3,addr) \
    asm volatile("ldmatrix.sync.aligned.m8n8.x4.shared.b16 {%0,%1,%2,%3}, [%4];" \
        : "=r"(r0), "=r"(r1), "=r"(r2), "=r"(r3) : "r"(addr))

#define MMA_F16(c, a0,a1,a2,a3, b0,b1) \
    asm volatile("mma.sync.aligned.m16n8k16.row.col.f32.f16.f16.f32 " \
        "{%0,%1,%2,%3}, {%4,%5,%6,%7}, {%8,%9}, {%0,%1,%2,%3};" \
        : "+f"((c)[0]), "+f"((c)[1]), "+f"((c)[2]), "+f"((c)[3]) \
        : "r"(a0), "r"(a1), "r"(a2), "r"(a3), "r"(b0), "r"(b1))

__device__ __forceinline__ void cp16(uint32_t dst, const void* src) {
    asm volatile("cp.async.cg.shared.global [%0], [%1], 16;" :: "r"(dst), "l"(src));
}
#define CP_COMMIT() asm volatile("cp.async.commit_group;" ::: "memory")
#define CP_WAIT(n)  asm volatile("cp.async.wait_group %0;" :: "n"(n) : "memory")

// fast e^{20x}: 2^{x*20*log2e}, degree-6 poly, relerr ~1e-7
__device__ __forceinline__ float exp20(float x) {
    float y = x * 28.853900817779268f;
    float z = y + 12582912.0f;
    int   zi = __float_as_int(z);
    float f = y - (z - 12582912.0f);
    float p = 1.5403530e-4f;
    p = fmaf(p, f, 1.3333558e-3f);
    p = fmaf(p, f, 9.6181291e-3f);
    p = fmaf(p, f, 5.5504109e-2f);
    p = fmaf(p, f, 2.4022651e-1f);
    p = fmaf(p, f, 6.9314718e-1f);
    p = fmaf(p, f, 1.0f);
    return __int_as_float(__float_as_int(p) + (zi << 23));
}

// ---------------- prep ----------------
__global__ void prep_kernel(const int* __restrict__ labraw) {
    __shared__ int is64_s;
    if (threadIdx.x == 0) {
        int all0 = 1;
        #pragma unroll
        for (int i = 0; i < 64; i++) all0 &= (labraw[2*i + 1] == 0);
        is64_s = all0;
    }
    __syncthreads();
    int is64 = is64_s;
    int tid = blockIdx.x*blockDim.x + threadIdx.x;
    int nt = gridDim.x*blockDim.x;
    for (int i = tid; i < BB; i += nt) g_lab[i] = is64 ? labraw[2*i] : labraw[i];
    for (int i = tid; i < NCLS*DD; i += nt) g_S[i] = 0.f;
    for (int i = tid; i < NCLS; i += nt) g_cnt[i] = 0;
    for (int i = tid; i < BB; i += nt) { g_hsum[i] = 0.f; g_hcnt[i] = 0; g_rowsum[i] = 0.f; }
    if (tid < 4) g_acc[tid] = 0.0;
    if (tid == 0) g_hn = 0;
}

// ---------------- normalize + fp16 cast + class sums ----------------
__global__ void norm_kernel(const float* __restrict__ feat) {
    int warp = threadIdx.x >> 5, lane = threadIdx.x & 31;
    int row = blockIdx.x*8 + warp;
    const float* fr = feat + (size_t)row*DD;
    float v[8]; float ss = 0.f;
    #pragma unroll
    for (int j = 0; j < 8; j++) { v[j] = fr[lane + j*32]; ss += v[j]*v[j]; }
    #pragma unroll
    for (int off = 16; off > 0; off >>= 1) ss += __shfl_xor_sync(0xffffffffu, ss, off);
    float inv = 1.f / fmaxf(sqrtf(ss), 1e-12f);
    int c = g_lab[row];
    #pragma unroll
    for (int j = 0; j < 8; j++) {
        float fnv = v[j]*inv;
        g_h[(size_t)row*DD + lane + j*32] = __float2half(fnv);
        atomicAdd(&g_S[c*DD + lane + j*32], fnv);
    }
    if (lane == 0) atomicAdd(&g_cnt[c], 1);
}

// ---------------- triangular fp16 mma.sync main kernel ----------------
// One 128x128 tile per CTA, rb <= cb. K chunked by 64, cp.async double-buffered,
// single __syncthreads per chunk.
#define KC 64
#define STR 72                       // 64 k elems + 8 pad (halves)
#define MAT (128*STR*2)              // 18432 B per matrix per stage
#define STAGE (2*MAT)                // A, B
#define SM_TOTAL (2*STAGE)           // 73728 B -> 2 CTAs/SM

__device__ __forceinline__ void load_chunk(uint32_t sb, int stage,
                                           int rowbase, int colbase, int kc) {
    int tid = threadIdx.x;
    uint32_t sbase = sb + stage*STAGE;
    #pragma unroll
    for (int m = 0; m < 2; m++) {
        int base = (m == 0) ? rowbase : colbase;
        #pragma unroll
        for (int i = 0; i < 4; i++) {
            int idx = tid + i*256;
            int row = idx >> 3;
            int kq = (idx & 7) * 8;
            uint32_t dst = sbase + m*MAT + (uint32_t)(row*STR + kq)*2;
            cp16(dst, &g_h[(size_t)(base+row)*DD + kc*KC + kq]);
        }
    }
}

__global__ void __launch_bounds__(256, 2)
main_tc() {
    extern __shared__ char smem[];
    uint32_t sb = smem_u32(smem);
    int tid = threadIdx.x;
    int wid = tid >> 5, l = tid & 31;
    int warpM = wid >> 2;
    int warpN = wid & 3;

    // decode triangular tile index -> (rb, cb), rb <= cb
    int rb = 0, rem = blockIdx.x;
    while (rem >= 64 - rb) { rem -= 64 - rb; rb++; }
    int cb = rb + rem;
    int rowbase = rb * 128;
    int colbase = cb * 128;
    bool isdiag = (rb == cb);

    uint32_t aOff = (uint32_t)((warpM*64 + (l & 15))*STR*2 + (l >> 4)*16);
    int bRow = (l & 7) + ((l >> 4) << 3);
    uint32_t bOff = (uint32_t)((warpN*32 + bRow)*STR*2 + ((l >> 3) & 1)*16);

    float acc[64];
    #pragma unroll
    for (int i = 0; i < 64; i++) acc[i] = 0.f;

    load_chunk(sb, 0, rowbase, colbase, 0);
    CP_COMMIT();

    #pragma unroll 1
    for (int c = 0; c < 4; ++c) {
        CP_WAIT(0);
        __syncthreads();
        if (c < 3) { load_chunk(sb, (c + 1) & 1, rowbase, colbase, c + 1); CP_COMMIT(); }

        uint32_t st = sb + (c & 1)*STAGE;
        uint32_t sA = st, sB = st + MAT;

        #pragma unroll
        for (int ks = 0; ks < 4; ++ks) {
            uint32_t ka = (uint32_t)(ks*32);
            uint32_t a0[16], b0[8];
            #pragma unroll
            for (int mt = 0; mt < 4; ++mt) {
                uint32_t aa = sA + aOff + (uint32_t)(mt*16*STR*2) + ka;
                LDM_X4(a0[mt*4+0], a0[mt*4+1], a0[mt*4+2], a0[mt*4+3], aa);
            }
            {
                uint32_t bb0 = sB + bOff + ka;
                uint32_t bb1 = bb0 + (uint32_t)(16*STR*2);
                LDM_X4(b0[0], b0[1], b0[2], b0[3], bb0);
                LDM_X4(b0[4], b0[5], b0[6], b0[7], bb1);
            }
            #pragma unroll
            for (int mt = 0; mt < 4; ++mt)
                #pragma unroll
                for (int nt = 0; nt < 4; ++nt)
                    MMA_F16(&acc[(mt*4+nt)*4], a0[mt*4+0], a0[mt*4+1], a0[mt*4+2], a0[mt*4+3],
                            b0[nt*2+0], b0[nt*2+1]);
        }
    }

    // ---- epilogue (inline rare-path, acc consumed in-loop) ----
    float rs[8];
    float cq0[4], cq1[4];
    #pragma unroll
    for (int i = 0; i < 8; i++) rs[i] = 0.f;
    #pragma unroll
    for (int i = 0; i < 4; i++) { cq0[i] = 0.f; cq1[i] = 0.f; }

    int grq = rowbase + warpM*64 + (l >> 2);
    #pragma unroll
    for (int mt = 0; mt < 4; ++mt) {
        int gr0 = grq + mt*16;
        int gr1 = gr0 + 8;
        #pragma unroll
        for (int nt = 0; nt < 4; ++nt) {
            const float* cc = &acc[(mt*4+nt)*4];
            int gc0 = colbase + warpN*32 + nt*8 + (l & 3)*2;
            int gc1 = gc0 + 1;
            float e0 = exp20(cc[0]);
            float e1 = exp20(cc[1]);
            float e2 = exp20(cc[2]);
            float e3 = exp20(cc[3]);
            if (isdiag) {
                e0 = (gc0 == gr0) ? 0.f : e0;
                e1 = (gc1 == gr0) ? 0.f : e1;
                e2 = (gc0 == gr1) ? 0.f : e2;
                e3 = (gc1 == gr1) ? 0.f : e3;
            }
            rs[mt*2+0] += e0 + e1;
            rs[mt*2+1] += e2 + e3;
            cq0[nt] += e0 + e2;
            cq1[nt] += e1 + e3;
            // rare path: cosine > 0.7, same label, not self
            if (cc[0] > 0.7f && gc0 != gr0 && g_lab[gc0] == g_lab[gr0]) {
                int idx = atomicAdd(&g_hn, 1);
                if (idx < HCAP) { g_hrow[idx] = gr0; g_hval[idx] = cc[0]*20.f; }
                if (!isdiag) {
                    int idx2 = atomicAdd(&g_hn, 1);
                    if (idx2 < HCAP) { g_hrow[idx2] = gc0; g_hval[idx2] = cc[0]*20.f; }
                }
            }
            if (cc[1] > 0.7f && gc1 != gr0 && g_lab[gc1] == g_lab[gr0]) {
                int idx = atomicAdd(&g_hn, 1);
                if (idx < HCAP) { g_hrow[idx] = gr0; g_hval[idx] = cc[1]*20.f; }
                if (!isdiag) {
                    int idx2 = atomicAdd(&g_hn, 1);
                    if (idx2 < HCAP) { g_hrow[idx2] = gc1; g_hval[idx2] = cc[1]*20.f; }
                }
            }
            if (cc[2] > 0.7f && gc0 != gr1 && g_lab[gc0] == g_lab[gr1]) {
                int idx = atomicAdd(&g_hn, 1);
                if (idx < HCAP) { g_hrow[idx] = gr1; g_hval[idx] = cc[2]*20.f; }
                if (!isdiag) {
                    int idx2 = atomicAdd(&g_hn, 1);
                    if (idx2 < HCAP) { g_hrow[idx2] = gc0; g_hval[idx2] = cc[2]*20.f; }
                }
            }
            if (cc[3] > 0.7f && gc1 != gr1 && g_lab[gc1] == g_lab[gr1]) {
                int idx = atomicAdd(&g_hn, 1);
                if (idx < HCAP) { g_hrow[idx] = gr1; g_hval[idx] = cc[3]*20.f; }
                if (!isdiag) {
                    int idx2 = atomicAdd(&g_hn, 1);
                    if (idx2 < HCAP) { g_hrow[idx2] = gc1; g_hval[idx2] = cc[3]*20.f; }
                }
            }
        }
    }

    // row sums: reduce over the 4 lanes in a quad (same rows), then atomic
    #pragma unroll
    for (int i = 0; i < 8; i++) {
        rs[i] += __shfl_xor_sync(0xffffffffu, rs[i], 1);
        rs[i] += __shfl_xor_sync(0xffffffffu, rs[i], 2);
    }
    if ((l & 3) == 0) {
        #pragma unroll
        for (int i = 0; i < 8; i++) {
            int row = rowbase + warpM*64 + (i >> 1)*16 + (i & 1)*8 + (l >> 2);
            atomicAdd(&g_rowsum[row], rs[i]);
        }
    }
    // column sums (symmetric contribution): reduce over the 8 lanes sharing columns
    if (!isdiag) {
        #pragma unroll
        for (int nt = 0; nt < 4; ++nt) {
            cq0[nt] += __shfl_xor_sync(0xffffffffu, cq0[nt], 4);
            cq0[nt] += __shfl_xor_sync(0xffffffffu, cq0[nt], 8);
            cq0[nt] += __shfl_xor_sync(0xffffffffu, cq0[nt], 16);
            cq1[nt] += __shfl_xor_sync(0xffffffffu, cq1[nt], 4);
            cq1[nt] += __shfl_xor_sync(0xffffffffu, cq1[nt], 8);
            cq1[nt] += __shfl_xor_sync(0xffffffffu, cq1[nt], 16);
        }
        if (l < 4) {
            #pragma unroll
            for (int nt = 0; nt < 4; ++nt) {
                int gc0 = colbase + warpN*32 + nt*8 + l*2;
                atomicAdd(&g_rowsum[gc0], cq0[nt]);
                atomicAdd(&g_rowsum[gc0 + 1], cq1[nt]);
            }
        }
    }
}

// ---------------- finalize A: parallel heavy reductions (grid 64) ----------------
__global__ void finalizeA_kernel() {
    int tid = threadIdx.x;
    int gt = blockIdx.x*256 + tid;       // 0..16383
    double accscl = 0.0;
    if (gt < BB) {
        float logd = logf(g_rowsum[gt] + 1e-30f);
        float np = (float)(g_cnt[g_lab[gt]] - 1);
        accscl = (double)np * (double)logd;
    }
    double lssq = 0.0;
    #pragma unroll
    for (int j = 0; j < 2; j++) {
        double s = (double)g_S[gt + j*16384];
        lssq += s*s;
    }
    double lcc = 0.0, lc2 = 0.0;
    if (gt < NCLS) {
        double cc = (double)g_cnt[gt];
        lcc = cc; lc2 = cc*cc;
    }
    __shared__ double s0[256], s1[256], s2[256], s3[256];
    s0[tid] = accscl; s1[tid] = lssq; s2[tid] = lcc; s3[tid] = lc2;
    __syncthreads();
    for (int st = 128; st > 0; st >>= 1) {
        if (tid < st) {
            s0[tid] += s0[tid+st]; s1[tid] += s1[tid+st];
            s2[tid] += s2[tid+st]; s3[tid] += s3[tid+st];
        }
        __syncthreads();
    }
    if (tid == 0) {
        atomicAdd(&g_acc[0], s0[0]);
        atomicAdd(&g_acc[1], s1[0]);
        atomicAdd(&g_acc[2], s2[0]);
        atomicAdd(&g_acc[3], s3[0]);
    }
}

// ---------------- finalize B: rare path + scalar combine ----------------
__global__ void finalizeB_kernel(float* __restrict__ out) {
    int tid = threadIdx.x;
    double accrel = 0.0;
    int hn = g_hn; if (hn > HCAP) hn = HCAP;
    if (hn > 0) {
        for (int e = tid; e < hn; e += 256) {
            int r = g_hrow[e];
            atomicAdd(&g_hsum[r], __expf(g_hval[e] - 20.f));
            atomicAdd(&g_hcnt[r], 1);
        }
        __syncthreads();
        for (int i = tid; i < BB; i += 256) {
            if (g_hcnt[i] > 0) accrel += (double)log1pf(g_hsum[i]);
        }
    }
    __shared__ double s2[256];
    s2[tid] = accrel;
    __syncthreads();
    for (int st = 128; st > 0; st >>= 1) {
        if (tid < st) s2[tid] += s2[tid+st];
        __syncthreads();
    }
    if (tid == 0) {
        double accscl = g_acc[0], ssq = g_acc[1], totc = g_acc[2], c2 = g_acc[3];
        double npos = c2 - totc;                    // sum cnt*(cnt-1)
        double possum = 20.0 * (ssq - totc);        // ordered positive-pair sim sum
        double scl = (npos > 0.0) ? (accscl - possum) / fmax(npos, 1.0) : 0.0;
        int hn2 = g_hn; if (hn2 > HCAP) hn2 = HCAP;
        double rel = (hn2 > 0) ? s2[0] / (double)(hn2 > 1 ? hn2 : 1) : 0.0;
        double tot = scl + rel;
        tot = fmin(fmax(tot, 0.0), 10.0);
        out[0] = (float)tot;
    }
}

extern "C" void kernel_launch(void* const* d_in, const int* in_sizes, int n_in,
                              void* d_out, int out_size) {
    const float* feat = (const float*)d_in[0];
    const int* labraw = (const int*)d_in[1];
    float* out = (float*)d_out;

    static bool attr_set = false;
    if (!attr_set) {
        cudaFuncSetAttribute(main_tc, cudaFuncAttributeMaxDynamicSharedMemorySize, SM_TOTAL);
        attr_set = true;
    }

    prep_kernel<<<64, 256>>>(labraw);
    norm_kernel<<<BB/8, 256>>>(feat);
    main_tc<<<2080, 256, SM_TOTAL>>>();
    finalizeA_kernel<<<64, 256>>>();
    finalizeB_kernel<<<1, 256>>>(out);
}